// round 4
// baseline (speedup 1.0000x reference)
#include <cuda_runtime.h>
#include <math.h>

#define N_SENT      262144
#define N_BAGS      4096
#define HIDDEN      256
#define NUM_CLASSES 53
#define RUN         64      // sentences per 64-thread subgroup in accum kernel

// Scratch (static __device__; no allocs allowed).
__device__ float2 g_logits[N_SENT];          // logits, then unnormalized e
__device__ float2 g_stats[N_BAGS];           // (1/sum0, 1/sum1)
__device__ float  g_repre[N_BAGS * 512];     // [B, 2*HIDDEN] accumulators

// ---------------------------------------------------------------------------
// K1: per-sentence logits. 4 sentences per warp -> 8 float4 loads in flight.
// ---------------------------------------------------------------------------
__global__ __launch_bounds__(256) void logits_kernel(
    const float4* __restrict__ x4,     // [N_SENT, 64]
    const float*  __restrict__ e0,     // [14, 256]
    const float*  __restrict__ e1,     // [53, 256]
    const int*    __restrict__ rl,     // [53, 2]
    const int*    __restrict__ li)     // [N_SENT]
{
    const int warp = threadIdx.x >> 5;
    const int lane = threadIdx.x & 31;
    const int base = (blockIdx.x * 8 + warp) * 4;   // grid 8192 covers N_SENT

    int c0 = __ldg(li + base + 0), c1 = __ldg(li + base + 1);
    int c2 = __ldg(li + base + 2), c3 = __ldg(li + base + 3);

    // 8 independent x loads issued up front.
    const float4* xp = x4 + (size_t)base * 64 + lane * 2;
    float4 xa0 = __ldg(xp),       xb0 = __ldg(xp + 1);
    float4 xa1 = __ldg(xp + 64),  xb1 = __ldg(xp + 65);
    float4 xa2 = __ldg(xp + 128), xb2 = __ldg(xp + 129);
    float4 xa3 = __ldg(xp + 192), xb3 = __ldg(xp + 193);

    float g0[4], g1[4];
    int cs[4] = {c0, c1, c2, c3};
    float4 XA[4] = {xa0, xa1, xa2, xa3};
    float4 XB[4] = {xb0, xb1, xb2, xb3};

    #pragma unroll
    for (int s = 0; s < 4; s++) {
        int l0 = __ldg(rl + 2 * cs[s]);
        int l1 = __ldg(rl + 2 * cs[s] + 1);
        const float4* p0 = reinterpret_cast<const float4*>(e0 + l0 * HIDDEN) + lane * 2;
        const float4* p1 = reinterpret_cast<const float4*>(e1 + l1 * HIDDEN) + lane * 2;
        float4 ea = __ldg(p0), eb = __ldg(p0 + 1);
        float4 fa = __ldg(p1), fb = __ldg(p1 + 1);
        float4 xa = XA[s], xb = XB[s];
        g0[s] = xa.x*ea.x + xa.y*ea.y + xa.z*ea.z + xa.w*ea.w
              + xb.x*eb.x + xb.y*eb.y + xb.z*eb.z + xb.w*eb.w;
        g1[s] = xa.x*fa.x + xa.y*fa.y + xa.z*fa.z + xa.w*fa.w
              + xb.x*fb.x + xb.y*fb.y + xb.z*fb.z + xb.w*fb.w;
    }

    #pragma unroll
    for (int s = 0; s < 4; s++) {
        #pragma unroll
        for (int o = 16; o; o >>= 1) {
            g0[s] += __shfl_xor_sync(0xffffffffu, g0[s], o);
            g1[s] += __shfl_xor_sync(0xffffffffu, g1[s], o);
        }
    }
    if (lane == 0) {
        g_logits[base + 0] = make_float2(g0[0], g1[0]);
        g_logits[base + 1] = make_float2(g0[1], g1[1]);
        g_logits[base + 2] = make_float2(g0[2], g1[2]);
        g_logits[base + 3] = make_float2(g0[3], g1[3]);
    }
}

// ---------------------------------------------------------------------------
// K2a: warp-per-bag softmax stats; rewrite g_logits with e = exp(lg - m);
//      store 1/sum. Also zero g_repre (grid-stride).
// ---------------------------------------------------------------------------
__global__ __launch_bounds__(256) void softmax_kernel(
    const int* __restrict__ scope)
{
    // Zero repre scratch: 2M floats over 512*256 threads.
    float4* rp = reinterpret_cast<float4*>(g_repre);
    int gt = blockIdx.x * 256 + threadIdx.x;
    #pragma unroll
    for (int k = 0; k < 4; k++)
        rp[gt + k * 131072] = make_float4(0.f, 0.f, 0.f, 0.f);

    const int warp = threadIdx.x >> 5;
    const int lane = threadIdx.x & 31;
    const int bag  = blockIdx.x * 8 + warp;   // grid 512 covers N_BAGS

    const int s0 = __ldg(scope + bag);
    const int s1 = __ldg(scope + bag + 1);

    float m0 = -INFINITY, m1 = -INFINITY;
    for (int i = s0 + lane; i < s1; i += 32) {
        float2 v = g_logits[i];
        m0 = fmaxf(m0, v.x);
        m1 = fmaxf(m1, v.y);
    }
    #pragma unroll
    for (int o = 16; o; o >>= 1) {
        m0 = fmaxf(m0, __shfl_xor_sync(0xffffffffu, m0, o));
        m1 = fmaxf(m1, __shfl_xor_sync(0xffffffffu, m1, o));
    }

    float sum0 = 0.f, sum1 = 0.f;
    for (int i = s0 + lane; i < s1; i += 32) {
        float2 v = g_logits[i];
        float e0v = __expf(v.x - m0);
        float e1v = __expf(v.y - m1);
        sum0 += e0v; sum1 += e1v;
        g_logits[i] = make_float2(e0v, e1v);
    }
    #pragma unroll
    for (int o = 16; o; o >>= 1) {
        sum0 += __shfl_xor_sync(0xffffffffu, sum0, o);
        sum1 += __shfl_xor_sync(0xffffffffu, sum1, o);
    }
    if (lane == 0)
        g_stats[bag] = make_float2(1.0f / sum0, 1.0f / sum1);
}

// ---------------------------------------------------------------------------
// K2b: sentence-parallel weighted accumulation. Each 64-thread subgroup owns
//      a fixed RUN-sentence range; accumulates per bag-segment in registers,
//      flushes with atomicAdd(inv * acc). Perfect load balance.
// ---------------------------------------------------------------------------
__global__ __launch_bounds__(256) void accum_kernel(
    const float4* __restrict__ x4,     // [N_SENT, 64]
    const int*    __restrict__ scope)  // [N_BAGS + 1]
{
    const int sub = threadIdx.x >> 6;          // 0..3
    const int d4  = threadIdx.x & 63;          // float4 column
    const int runStart = (blockIdx.x * 4 + sub) * RUN;   // grid 1024
    const int runEnd   = runStart + RUN;

    // largest bag with scope[bag] <= runStart
    int lo = 0, hi = N_BAGS;
    while (lo < hi) {
        int mid = (lo + hi + 1) >> 1;
        if (__ldg(scope + mid) <= runStart) lo = mid; else hi = mid - 1;
    }
    int bag = lo;

    int j = runStart;
    while (j < runEnd) {
        int e = __ldg(scope + bag + 1);
        while (e <= j) { bag++; e = __ldg(scope + bag + 1); }
        int j1 = min(runEnd, e);

        float4 a0 = make_float4(0.f, 0.f, 0.f, 0.f);
        float4 a1 = make_float4(0.f, 0.f, 0.f, 0.f);
        #pragma unroll 4
        for (int t = j; t < j1; t++) {
            float2 w  = *(const float2*)&g_logits[t];   // broadcast
            float4 xv = __ldg(x4 + (size_t)t * 64 + d4);
            a0.x += w.x * xv.x; a0.y += w.x * xv.y;
            a0.z += w.x * xv.z; a0.w += w.x * xv.w;
            a1.x += w.y * xv.x; a1.y += w.y * xv.y;
            a1.z += w.y * xv.z; a1.w += w.y * xv.w;
        }

        float2 iv = g_stats[bag];
        float* r0 = &g_repre[bag * 512 + d4 * 4];
        atomicAdd(r0 + 0, iv.x * a0.x);
        atomicAdd(r0 + 1, iv.x * a0.y);
        atomicAdd(r0 + 2, iv.x * a0.z);
        atomicAdd(r0 + 3, iv.x * a0.w);
        float* r1 = r0 + 256;
        atomicAdd(r1 + 0, iv.y * a1.x);
        atomicAdd(r1 + 1, iv.y * a1.y);
        atomicAdd(r1 + 2, iv.y * a1.z);
        atomicAdd(r1 + 3, iv.y * a1.w);

        j = j1;
    }
}

// ---------------------------------------------------------------------------
// K3: out[b, r] = <repre[b], disc[r]> + bias[r]. disc tiled into static smem
//     (18 classes per tile, fits 48KB static); 16 bags per block.
// ---------------------------------------------------------------------------
#define K3_BAGS 16
#define K3_CLS  18
__global__ __launch_bounds__(256) void out_kernel(
    const float* __restrict__ disc,    // [53, 512]
    const float* __restrict__ bias,    // [53]
    float*       __restrict__ out)     // [N_BAGS, 53]
{
    __shared__ float s_disc[K3_CLS * 512];
    __shared__ float s_re[512];

    const int tid  = threadIdx.x;
    const int lane = tid & 31;
    const int warp = tid >> 5;

    const int grp    = blockIdx.x / (N_BAGS / K3_BAGS);   // class-group 0..2
    const int bagBlk = blockIdx.x % (N_BAGS / K3_BAGS);
    const int rBeg = grp * K3_CLS;
    const int rEnd = min(NUM_CLASSES, rBeg + K3_CLS);
    const int nCls = rEnd - rBeg;

    for (int k = tid; k < nCls * 512; k += 256)
        s_disc[k] = __ldg(disc + rBeg * 512 + k);

    const int bag0 = bagBlk * K3_BAGS;
    for (int bb = 0; bb < K3_BAGS; bb++) {
        const int b = bag0 + bb;
        __syncthreads();
        s_re[tid]       = g_repre[b * 512 + tid];
        s_re[256 + tid] = g_repre[b * 512 + 256 + tid];
        __syncthreads();

        float rv[16];
        #pragma unroll
        for (int i = 0; i < 16; i++) rv[i] = s_re[lane + 32 * i];

        for (int r = warp; r < nCls; r += 8) {
            float sum = 0.f;
            #pragma unroll
            for (int i = 0; i < 16; i++)
                sum += rv[i] * s_disc[r * 512 + lane + 32 * i];
            #pragma unroll
            for (int o = 16; o; o >>= 1)
                sum += __shfl_xor_sync(0xffffffffu, sum, o);
            if (lane == 0)
                out[b * NUM_CLASSES + rBeg + r] = sum + __ldg(bias + rBeg + r);
        }
    }
}

// ---------------------------------------------------------------------------
extern "C" void kernel_launch(void* const* d_in, const int* in_sizes, int n_in,
                              void* d_out, int out_size)
{
    const float* x    = (const float*)d_in[0];   // [262144, 256]
    const float* e0   = (const float*)d_in[1];   // [14, 256]
    const float* e1   = (const float*)d_in[2];   // [53, 256]
    const float* disc = (const float*)d_in[3];   // [53, 512]
    const float* bias = (const float*)d_in[4];   // [53]
    const int*   rl   = (const int*)d_in[5];     // [53, 2]
    const int*   li   = (const int*)d_in[6];     // [262144]
    const int*   sc   = (const int*)d_in[7];     // [4097]
    float* out = (float*)d_out;                  // [4096, 53]

    logits_kernel<<<N_SENT / 32, 256>>>((const float4*)x, e0, e1, rl, li);
    softmax_kernel<<<N_BAGS / 8, 256>>>(sc);
    accum_kernel<<<N_SENT / (4 * RUN), 256>>>((const float4*)x, sc);
    out_kernel<<<3 * (N_BAGS / K3_BAGS), 256>>>(disc, bias, out);
}

// round 5
// speedup vs baseline: 1.1951x; 1.1951x over previous
#include <cuda_runtime.h>
#include <math.h>

#define N_SENT      262144
#define N_BAGS      4096
#define HIDDEN      256
#define NUM_CLASSES 53
#define CH          512   // weight chunk (sentences) staged in smem per iteration

// Per-sentence logits scratch (static __device__; no allocs allowed).
__device__ float2 g_logits[N_SENT];

// ---------------------------------------------------------------------------
// K1: per-sentence logits. 4 sentences per warp -> 8 float4 loads in flight.
// ---------------------------------------------------------------------------
__global__ __launch_bounds__(256) void logits_kernel(
    const float4* __restrict__ x4,     // [N_SENT, 64]
    const float*  __restrict__ e0,     // [14, 256]
    const float*  __restrict__ e1,     // [53, 256]
    const int*    __restrict__ rl,     // [53, 2]
    const int*    __restrict__ li)     // [N_SENT]
{
    const int warp = threadIdx.x >> 5;
    const int lane = threadIdx.x & 31;
    const int base = (blockIdx.x * 8 + warp) * 4;   // grid 8192 covers N_SENT

    int cs[4];
    #pragma unroll
    for (int s = 0; s < 4; s++) cs[s] = __ldg(li + base + s);

    // 8 independent x loads issued up front.
    const float4* xp = x4 + (size_t)base * 64 + lane * 2;
    float4 XA[4], XB[4];
    #pragma unroll
    for (int s = 0; s < 4; s++) {
        XA[s] = __ldg(xp + s * 64);
        XB[s] = __ldg(xp + s * 64 + 1);
    }

    float g0[4], g1[4];
    #pragma unroll
    for (int s = 0; s < 4; s++) {
        int l0 = __ldg(rl + 2 * cs[s]);
        int l1 = __ldg(rl + 2 * cs[s] + 1);
        const float4* p0 = reinterpret_cast<const float4*>(e0 + l0 * HIDDEN) + lane * 2;
        const float4* p1 = reinterpret_cast<const float4*>(e1 + l1 * HIDDEN) + lane * 2;
        float4 ea = __ldg(p0), eb = __ldg(p0 + 1);
        float4 fa = __ldg(p1), fb = __ldg(p1 + 1);
        float4 xa = XA[s], xb = XB[s];
        g0[s] = xa.x*ea.x + xa.y*ea.y + xa.z*ea.z + xa.w*ea.w
              + xb.x*eb.x + xb.y*eb.y + xb.z*eb.z + xb.w*eb.w;
        g1[s] = xa.x*fa.x + xa.y*fa.y + xa.z*fa.z + xa.w*fa.w
              + xb.x*fb.x + xb.y*fb.y + xb.z*fb.z + xb.w*fb.w;
    }

    #pragma unroll
    for (int s = 0; s < 4; s++) {
        #pragma unroll
        for (int o = 16; o; o >>= 1) {
            g0[s] += __shfl_xor_sync(0xffffffffu, g0[s], o);
            g1[s] += __shfl_xor_sync(0xffffffffu, g1[s], o);
        }
    }
    if (lane == 0) {
        #pragma unroll
        for (int s = 0; s < 4; s++)
            g_logits[base + s] = make_float2(g0[s], g1[s]);
    }
}

// ---------------------------------------------------------------------------
// K2: one block per bag. Softmax from g_logits -> staged weights in smem ->
//     float4 weighted sum (4 sentence subgroups x 64 float4 columns) ->
//     fused epilogue GEMM.
// ---------------------------------------------------------------------------
__global__ __launch_bounds__(256) void bag_kernel(
    const float4* __restrict__ x4,     // [N_SENT, 64]
    const float*  __restrict__ disc,   // [53, 512]
    const float*  __restrict__ bias,   // [53]
    const int*    __restrict__ scope,  // [N_BAGS + 1]
    float*        __restrict__ out)    // [N_BAGS, 53]
{
    __shared__ float2 s_w[CH];
    __shared__ float  s_red[16];
    __shared__ float  s_re[2 * HIDDEN];

    const int b    = blockIdx.x;
    const int tid  = threadIdx.x;
    const int lane = tid & 31;
    const int warp = tid >> 5;

    const int s0 = __ldg(scope + b);
    const int s1 = __ldg(scope + b + 1);
    const int n  = s1 - s0;

    // ---- softmax stats from g_logits ----
    float lm0 = -INFINITY, lm1 = -INFINITY;
    for (int i = tid; i < n; i += 256) {
        float2 v = g_logits[s0 + i];
        lm0 = fmaxf(lm0, v.x);
        lm1 = fmaxf(lm1, v.y);
    }
    #pragma unroll
    for (int o = 16; o; o >>= 1) {
        lm0 = fmaxf(lm0, __shfl_xor_sync(0xffffffffu, lm0, o));
        lm1 = fmaxf(lm1, __shfl_xor_sync(0xffffffffu, lm1, o));
    }
    if (lane == 0) { s_red[warp] = lm0; s_red[8 + warp] = lm1; }
    __syncthreads();
    float m0 = s_red[0], m1 = s_red[8];
    #pragma unroll
    for (int k = 1; k < 8; k++) {
        m0 = fmaxf(m0, s_red[k]);
        m1 = fmaxf(m1, s_red[8 + k]);
    }
    __syncthreads();

    float ls0 = 0.f, ls1 = 0.f;
    for (int i = tid; i < n; i += 256) {
        float2 v = g_logits[s0 + i];
        ls0 += __expf(v.x - m0);
        ls1 += __expf(v.y - m1);
    }
    #pragma unroll
    for (int o = 16; o; o >>= 1) {
        ls0 += __shfl_xor_sync(0xffffffffu, ls0, o);
        ls1 += __shfl_xor_sync(0xffffffffu, ls1, o);
    }
    if (lane == 0) { s_red[warp] = ls0; s_red[8 + warp] = ls1; }
    __syncthreads();
    float sum0 = 0.f, sum1 = 0.f;
    #pragma unroll
    for (int k = 0; k < 8; k++) { sum0 += s_red[k]; sum1 += s_red[8 + k]; }
    const float inv0 = 1.0f / sum0;   // empty bag: inf, but loop below is no-op
    const float inv1 = 1.0f / sum1;

    // ---- weighted accumulation: sg = sentence subgroup, d4 = float4 column ----
    const int sg = tid >> 6;           // 0..3
    const int d4 = tid & 63;           // 0..63
    float4 a0 = make_float4(0.f, 0.f, 0.f, 0.f);
    float4 a1 = make_float4(0.f, 0.f, 0.f, 0.f);

    for (int cs = 0; cs < n; cs += CH) {
        int cn = min(CH, n - cs);
        __syncthreads();
        for (int i = tid; i < cn; i += 256) {
            float2 v = g_logits[s0 + cs + i];
            s_w[i] = make_float2(__expf(v.x - m0) * inv0,
                                 __expf(v.y - m1) * inv1);
        }
        __syncthreads();

        const float4* xb = x4 + (size_t)(s0 + cs) * 64 + d4;
        int j = sg;
        // unroll-4 over the subgroup's sentences: 4 float4 loads in flight
        for (; j + 12 < cn; j += 16) {
            float4 x0 = __ldg(xb + (size_t)(j)      * 64);
            float4 x1 = __ldg(xb + (size_t)(j + 4)  * 64);
            float4 x2 = __ldg(xb + (size_t)(j + 8)  * 64);
            float4 x3 = __ldg(xb + (size_t)(j + 12) * 64);
            float2 w0 = s_w[j], w1 = s_w[j + 4], w2 = s_w[j + 8], w3 = s_w[j + 12];
            a0.x += w0.x*x0.x; a0.y += w0.x*x0.y; a0.z += w0.x*x0.z; a0.w += w0.x*x0.w;
            a1.x += w0.y*x0.x; a1.y += w0.y*x0.y; a1.z += w0.y*x0.z; a1.w += w0.y*x0.w;
            a0.x += w1.x*x1.x; a0.y += w1.x*x1.y; a0.z += w1.x*x1.z; a0.w += w1.x*x1.w;
            a1.x += w1.y*x1.x; a1.y += w1.y*x1.y; a1.z += w1.y*x1.z; a1.w += w1.y*x1.w;
            a0.x += w2.x*x2.x; a0.y += w2.x*x2.y; a0.z += w2.x*x2.z; a0.w += w2.x*x2.w;
            a1.x += w2.y*x2.x; a1.y += w2.y*x2.y; a1.z += w2.y*x2.z; a1.w += w2.y*x2.w;
            a0.x += w3.x*x3.x; a0.y += w3.x*x3.y; a0.z += w3.x*x3.z; a0.w += w3.x*x3.w;
            a1.x += w3.y*x3.x; a1.y += w3.y*x3.y; a1.z += w3.y*x3.z; a1.w += w3.y*x3.w;
        }
        for (; j < cn; j += 4) {
            float4 xv = __ldg(xb + (size_t)j * 64);
            float2 w  = s_w[j];
            a0.x += w.x*xv.x; a0.y += w.x*xv.y; a0.z += w.x*xv.z; a0.w += w.x*xv.w;
            a1.x += w.y*xv.x; a1.y += w.y*xv.y; a1.z += w.y*xv.z; a1.w += w.y*xv.w;
        }
    }

    // ---- combine 4 subgroups into s_re ----
    __syncthreads();
    s_re[tid]       = 0.f;
    s_re[256 + tid] = 0.f;
    __syncthreads();
    #pragma unroll
    for (int g = 0; g < 4; g++) {
        if (sg == g) {
            int base = d4 * 4;
            s_re[base + 0] += a0.x; s_re[base + 1] += a0.y;
            s_re[base + 2] += a0.z; s_re[base + 3] += a0.w;
            s_re[256 + base + 0] += a1.x; s_re[256 + base + 1] += a1.y;
            s_re[256 + base + 2] += a1.z; s_re[256 + base + 3] += a1.w;
        }
        __syncthreads();
    }

    // ---- fused epilogue GEMM: out[b, r] = <stack_repre, disc[r]> + bias[r] ----
    for (int r = warp; r < NUM_CLASSES; r += 8) {
        float sum = 0.f;
        #pragma unroll
        for (int k = lane; k < 2 * HIDDEN; k += 32)
            sum += s_re[k] * __ldg(disc + r * (2 * HIDDEN) + k);
        #pragma unroll
        for (int o = 16; o; o >>= 1)
            sum += __shfl_xor_sync(0xffffffffu, sum, o);
        if (lane == 0)
            out[b * NUM_CLASSES + r] = sum + __ldg(bias + r);
    }
}

// ---------------------------------------------------------------------------
extern "C" void kernel_launch(void* const* d_in, const int* in_sizes, int n_in,
                              void* d_out, int out_size)
{
    const float* x    = (const float*)d_in[0];   // [262144, 256]
    const float* e0   = (const float*)d_in[1];   // [14, 256]
    const float* e1   = (const float*)d_in[2];   // [53, 256]
    const float* disc = (const float*)d_in[3];   // [53, 512]
    const float* bias = (const float*)d_in[4];   // [53]
    const int*   rl   = (const int*)d_in[5];     // [53, 2]
    const int*   li   = (const int*)d_in[6];     // [262144]
    const int*   sc   = (const int*)d_in[7];     // [4097]
    float* out = (float*)d_out;                  // [4096, 53]

    logits_kernel<<<N_SENT / 32, 256>>>((const float4*)x, e0, e1, rl, li);
    bag_kernel<<<N_BAGS, 256>>>((const float4*)x, disc, bias, sc, out);
}